// round 1
// baseline (speedup 1.0000x reference)
#include <cuda_runtime.h>
#include <cuda_bf16.h>

#define TT 8192
#define DD 64
#define MM 4

// ---------------- scratch (device globals; no allocation) ----------------
__device__ float g_Q [TT * DD];            // Q row-major [t][d]           2MB
__device__ float g_KT[MM * DD * TT];       // K transposed [m][d][t]       8MB
__device__ float g_V2[MM * TT * 2];        // V interleaved [m][t][e]      256KB
__device__ float g_T2[MM * TT];            // t2 per modality (t1 = m=0)
__device__ int   g_idx[MM * TT];
__device__ float g_S [MM * DD * TT * 2];   // prefix sums [m][d][t][e]     16MB
__device__ float g_part[8 * TT * 2];       // partials [(m,dhalf)][t][e]

// ---------------- packed f32x2 helpers ----------------
__device__ __forceinline__ unsigned long long pack2(float lo, float hi) {
    unsigned long long r;
    asm("mov.b64 %0, {%1, %2};" : "=l"(r) : "f"(lo), "f"(hi));
    return r;
}
__device__ __forceinline__ unsigned long long fma2(unsigned long long a,
                                                   unsigned long long b,
                                                   unsigned long long c) {
    unsigned long long d;
    asm("fma.rn.f32x2 %0, %1, %2, %3;" : "=l"(d) : "l"(a), "l"(b), "l"(c));
    return d;
}
__device__ __forceinline__ float2 unpack2(unsigned long long v) {
    float2 r;
    asm("mov.b64 {%0, %1}, %2;" : "=f"(r.x), "=f"(r.y) : "l"(v));
    return r;
}

// ---------------- Kernel 1: the 5 MLPs (Q and K_0..K_3) ----------------
// grid (T/128, 5), 256 threads. Thread computes 4 rows (strided 32) x 8 cols
// (2 cols packed per f32x2 accumulator). A tile k-major in smem (pad 129).
__global__ void __launch_bounds__(256) k_mlp(
    const float* __restrict__ X,
    const float* __restrict__ wq_w, const float* __restrict__ wq_b,
    const float* __restrict__ wk_w, const float* __restrict__ wk_b)
{
    extern __shared__ float sm[];
    float* As = sm;              // 64 * 129 floats
    float* Ws = sm + 64 * 129;   // 64 * 64 floats

    const int tid  = threadIdx.x;
    const int u    = blockIdx.y;                 // 0 -> Q, 1..4 -> K_{u-1}
    const int base = blockIdx.x * 128;
    const int m_in = (u == 0) ? 0 : (u - 1);
    const float* W = (u == 0) ? wq_w : wk_w + (size_t)(u - 1) * 3 * DD * DD;
    const float* B = (u == 0) ? wq_b : wk_b + (size_t)(u - 1) * 3 * DD;

    // load A tile transposed into smem: As[d][row]
    {
        const int row = tid & 127;
        const int dh  = tid >> 7;   // 0 or 1 (which 32-channel half)
        const float4* src = (const float4*)(X + ((size_t)m_in * TT + base + row) * DD + dh * 32);
        #pragma unroll
        for (int q = 0; q < 8; q++) {
            float4 v = src[q];
            int d0 = dh * 32 + q * 4;
            As[(d0 + 0) * 129 + row] = v.x;
            As[(d0 + 1) * 129 + row] = v.y;
            As[(d0 + 2) * 129 + row] = v.z;
            As[(d0 + 3) * 129 + row] = v.w;
        }
    }

    const int rg = tid & 31;   // row group: rows rg + 32*i
    const int cg = tid >> 5;   // col group: cols cg*8 .. cg*8+7

    for (int l = 0; l < 3; l++) {
        __syncthreads();
        // load this layer's weights (64x64)
        {
            const float4* wsrc = (const float4*)(W + (size_t)l * DD * DD);
            for (int i = tid; i < DD * DD / 4; i += 256)
                ((float4*)Ws)[i] = wsrc[i];
        }
        __syncthreads();

        unsigned long long acc2[4][4];
        #pragma unroll
        for (int i = 0; i < 4; i++)
            #pragma unroll
            for (int jp = 0; jp < 4; jp++) acc2[i][jp] = 0ULL;

        #pragma unroll 8
        for (int k = 0; k < 64; k++) {
            unsigned long long a2[4];
            #pragma unroll
            for (int i = 0; i < 4; i++) {
                float a = As[k * 129 + rg + 32 * i];
                a2[i] = pack2(a, a);
            }
            const unsigned long long* wv =
                (const unsigned long long*)(Ws + k * 64 + cg * 8);
            #pragma unroll
            for (int jp = 0; jp < 4; jp++) {
                unsigned long long w2 = wv[jp];
                #pragma unroll
                for (int i = 0; i < 4; i++)
                    acc2[i][jp] = fma2(a2[i], w2, acc2[i][jp]);
            }
        }

        __syncthreads();   // all reads of As done before overwrite

        #pragma unroll
        for (int i = 0; i < 4; i++) {
            const int row = rg + 32 * i;
            #pragma unroll
            for (int jp = 0; jp < 4; jp++) {
                float2 v  = unpack2(acc2[i][jp]);
                const int j0 = cg * 8 + jp * 2;
                float2 bb = *(const float2*)(B + l * 64 + j0);
                float o0 = v.x + bb.x;
                float o1 = v.y + bb.y;
                if (l < 2) {
                    o0 = fmaxf(o0, 0.0f);
                    o1 = fmaxf(o1, 0.0f);
                    As[(j0 + 0) * 129 + row] = o0;
                    As[(j0 + 1) * 129 + row] = o1;
                } else if (u == 0) {
                    *(float2*)(g_Q + (size_t)(base + row) * 64 + j0) = make_float2(o0, o1);
                } else {
                    g_KT[(size_t)((u - 1) * 64 + j0    ) * TT + base + row] = o0;
                    g_KT[(size_t)((u - 1) * 64 + j0 + 1) * TT + base + row] = o1;
                }
            }
        }
    }
}

// ---------------- Kernel 2: extract V (channels 0,1) and times ----------------
__global__ void __launch_bounds__(256) k_prep(const float* __restrict__ X)
{
    const int m = blockIdx.y;
    const int t = blockIdx.x * 256 + threadIdx.x;
    const float* xr = X + ((size_t)m * TT + t) * DD;
    float2 v;
    v.x = xr[0];
    v.y = xr[1];
    ((float2*)g_V2)[(size_t)m * TT + t] = v;
    g_T2[(size_t)m * TT + t] = xr[63];
}

// ---------------- Kernel 3: searchsorted(t2_m, t1, right) - 1 ----------------
__global__ void __launch_bounds__(256) k_idx()
{
    const int m = blockIdx.y;
    const int t = blockIdx.x * 256 + threadIdx.x;
    const float key = g_T2[t];              // t1[t] = g_T2[0*T + t]
    const float* arr = g_T2 + (size_t)m * TT;
    int lo = 0, hi = TT;
    while (lo < hi) {
        int mid = (lo + hi) >> 1;
        if (arr[mid] <= key) lo = mid + 1; else hi = mid;
    }
    g_idx[(size_t)m * TT + t] = lo - 1;
}

// ---------------- Kernel 4: blocked prefix scan per (m, d) channel ----------------
// One block per (m,d). S[m][d][t][e] = sum_{j<=t} K[m][j][d] * V[m][j][e], e in {0,1}.
__global__ void __launch_bounds__(256) k_scan()
{
    const int m = blockIdx.x >> 6;
    const int d = blockIdx.x & 63;
    const float4* kp = (const float4*)(g_KT + (size_t)(m * 64 + d) * TT);
    const float4* vp = (const float4*)(g_V2 + (size_t)m * TT * 2);
    float4* sp = (float4*)(g_S + (size_t)(m * 64 + d) * TT * 2);

    __shared__ float ws0[8], ws1[8];
    const int tid = threadIdx.x, lane = tid & 31, wid = tid >> 5;
    float c0 = 0.0f, c1 = 0.0f;

    for (int chunk = 0; chunk < TT; chunk += 2048) {
        const int b8 = chunk + tid * 8;   // this thread's 8 elements
        float4 ka = kp[b8 / 4], kb = kp[b8 / 4 + 1];
        float kk[8] = {ka.x, ka.y, ka.z, ka.w, kb.x, kb.y, kb.z, kb.w};
        float p0[8], p1[8];
        #pragma unroll
        for (int e = 0; e < 4; e++) {
            float4 v = vp[b8 / 2 + e];   // (v0,v1) for elems 2e, 2e+1
            p0[2 * e]     = kk[2 * e]     * v.x;
            p1[2 * e]     = kk[2 * e]     * v.y;
            p0[2 * e + 1] = kk[2 * e + 1] * v.z;
            p1[2 * e + 1] = kk[2 * e + 1] * v.w;
        }
        #pragma unroll
        for (int e = 1; e < 8; e++) { p0[e] += p0[e - 1]; p1[e] += p1[e - 1]; }
        const float t0 = p0[7], t1 = p1[7];

        // warp inclusive scan of thread totals
        float s0 = t0, s1 = t1;
        #pragma unroll
        for (int off = 1; off < 32; off <<= 1) {
            float n0 = __shfl_up_sync(0xffffffffu, s0, off);
            float n1 = __shfl_up_sync(0xffffffffu, s1, off);
            if (lane >= off) { s0 += n0; s1 += n1; }
        }
        if (lane == 31) { ws0[wid] = s0; ws1[wid] = s1; }
        __syncthreads();

        float off0 = 0, off1 = 0, tot0 = 0, tot1 = 0;
        #pragma unroll
        for (int w = 0; w < 8; w++) {
            float a = ws0[w], b = ws1[w];
            if (w < wid) { off0 += a; off1 += b; }
            tot0 += a; tot1 += b;
        }
        const float base0 = c0 + off0 + (s0 - t0);
        const float base1 = c1 + off1 + (s1 - t1);

        #pragma unroll
        for (int e = 0; e < 4; e++) {
            float4 o;
            o.x = base0 + p0[2 * e];     o.y = base1 + p1[2 * e];
            o.z = base0 + p0[2 * e + 1]; o.w = base1 + p1[2 * e + 1];
            sp[b8 / 2 + e] = o;
        }
        c0 += tot0; c1 += tot1;
        __syncthreads();   // protect ws before next chunk
    }
}

// ---------------- Kernel 5: gather + contract  out_m[t,e] = sum_d Q[t,d] S[m][d][idx][e]
// grid (T/128, M), 256 threads: thread = (t_local, d_half of 32).
__global__ void __launch_bounds__(256) k_gather()
{
    __shared__ float Qs[128 * 65];
    const int m  = blockIdx.y;
    const int t0 = blockIdx.x * 128;

    for (int i = threadIdx.x; i < 128 * 64; i += 256) {
        int r = i >> 6, dd = i & 63;
        Qs[r * 65 + dd] = g_Q[(size_t)(t0 + r) * 64 + dd];
    }
    __syncthreads();

    const int lt = threadIdx.x & 127;
    const int dh = threadIdx.x >> 7;
    const int t  = t0 + lt;
    const int idx = g_idx[(size_t)m * TT + t];

    float a0 = 0.0f, a1 = 0.0f;
    if (idx >= 0) {
        const float2* sp = (const float2*)g_S;
        #pragma unroll
        for (int dd = 0; dd < 32; dd++) {
            const int d = dh * 32 + dd;
            float q  = Qs[lt * 65 + d];
            float2 s = sp[(size_t)(m * 64 + d) * TT + idx];
            a0 += q * s.x;
            a1 += q * s.y;
        }
    }
    g_part[((size_t)(m * 2 + dh) * TT + t) * 2 + 0] = a0;
    g_part[((size_t)(m * 2 + dh) * TT + t) * 2 + 1] = a1;
}

// ---------------- Kernel 6: deterministic reduction over 8 partials ----------------
__global__ void __launch_bounds__(256) k_reduce(float* __restrict__ out)
{
    const int t = blockIdx.x * 256 + threadIdx.x;   // t in [0, T)
    const float2* pp = (const float2*)g_part;
    float ax = 0.0f, ay = 0.0f;
    #pragma unroll
    for (int s = 0; s < 8; s++) {
        float2 v = pp[(size_t)s * TT + t];
        ax += v.x; ay += v.y;
    }
    ((float2*)out)[t] = make_float2(ax, ay);
}

// ---------------- launch ----------------
extern "C" void kernel_launch(void* const* d_in, const int* in_sizes, int n_in,
                              void* d_out, int out_size)
{
    const float* X    = (const float*)d_in[0];
    const float* wq_w = (const float*)d_in[1];
    const float* wq_b = (const float*)d_in[2];
    const float* wk_w = (const float*)d_in[3];
    const float* wk_b = (const float*)d_in[4];
    float* out = (float*)d_out;

    const int SMEM1 = (64 * 129 + 64 * 64) * (int)sizeof(float);   // 49408 B
    cudaFuncSetAttribute(k_mlp, cudaFuncAttributeMaxDynamicSharedMemorySize, SMEM1);

    k_mlp   <<<dim3(TT / 128, 5), 256, SMEM1>>>(X, wq_w, wq_b, wk_w, wk_b);
    k_prep  <<<dim3(TT / 256, MM), 256>>>(X);
    k_idx   <<<dim3(TT / 256, MM), 256>>>();
    k_scan  <<<MM * DD, 256>>>();
    k_gather<<<dim3(TT / 128, MM), 256>>>();
    k_reduce<<<TT / 256, 256>>>(out);
}

// round 2
// speedup vs baseline: 1.0395x; 1.0395x over previous
#include <cuda_runtime.h>
#include <cuda_bf16.h>

#define TT 8192
#define DD 64
#define MM 4
#define NSEG 8
#define SEG 1024

// ---------------- scratch (device globals; no allocation) ----------------
__device__ float g_Q [TT * DD];            // Q row-major [t][d]           2MB
__device__ float g_KT[MM * DD * TT];       // K transposed [m][d][t]       8MB
__device__ float g_V2[MM * TT * 2];        // V interleaved [m][t][e]      256KB
__device__ float g_T2[MM * TT];            // t2 per modality (t1 = m=0)
__device__ float g_S [MM * DD * TT * 2];   // prefix sums [m][d][t][e]     16MB
__device__ float g_seg[MM * DD * NSEG * 2];// per-segment totals
__device__ float g_part[8 * TT * 2];       // partials [(m,dhalf)][t][e]

// ---------------- packed f32x2 helpers ----------------
__device__ __forceinline__ unsigned long long pack2(float lo, float hi) {
    unsigned long long r;
    asm("mov.b64 %0, {%1, %2};" : "=l"(r) : "f"(lo), "f"(hi));
    return r;
}
__device__ __forceinline__ unsigned long long fma2(unsigned long long a,
                                                   unsigned long long b,
                                                   unsigned long long c) {
    unsigned long long d;
    asm("fma.rn.f32x2 %0, %1, %2, %3;" : "=l"(d) : "l"(a), "l"(b), "l"(c));
    return d;
}
__device__ __forceinline__ float2 unpack2(unsigned long long v) {
    float2 r;
    asm("mov.b64 {%0, %1}, %2;" : "=f"(r.x), "=f"(r.y) : "l"(v));
    return r;
}

// ---------------- Kernel 1: the 5 MLPs (Q and K_0..K_3) ----------------
// grid (T/64, 5), 256 threads. 64-row tiles for finer wave granularity.
// Thread computes 2 rows (rg, rg+32) x 8 cols (4 packed f32x2 accumulators).
__global__ void __launch_bounds__(256) k_mlp(
    const float* __restrict__ X,
    const float* __restrict__ wq_w, const float* __restrict__ wq_b,
    const float* __restrict__ wk_w, const float* __restrict__ wk_b)
{
    extern __shared__ float sm[];
    float* As = sm;              // 64 * 65 floats (As[d][row])
    float* Ws = sm + 64 * 65;    // 64 * 64 floats

    const int tid  = threadIdx.x;
    const int u    = blockIdx.y;                 // 0 -> Q, 1..4 -> K_{u-1}
    const int base = blockIdx.x * 64;
    const int m_in = (u == 0) ? 0 : (u - 1);
    const float* W = (u == 0) ? wq_w : wk_w + (size_t)(u - 1) * 3 * DD * DD;
    const float* B = (u == 0) ? wq_b : wk_b + (size_t)(u - 1) * 3 * DD;

    // load 64x64 A tile transposed into smem: As[d][row]
    {
        const int row = tid >> 2;          // 0..63
        const int qi  = tid & 3;           // 16-float chunk
        const float4* src = (const float4*)(X + ((size_t)m_in * TT + base + row) * DD + qi * 16);
        #pragma unroll
        for (int q = 0; q < 4; q++) {
            float4 v = src[q];
            int d0 = qi * 16 + q * 4;
            As[(d0 + 0) * 65 + row] = v.x;
            As[(d0 + 1) * 65 + row] = v.y;
            As[(d0 + 2) * 65 + row] = v.z;
            As[(d0 + 3) * 65 + row] = v.w;
        }
    }

    const int rg = tid & 31;   // rows rg, rg+32
    const int cg = tid >> 5;   // cols cg*8 .. cg*8+7

    for (int l = 0; l < 3; l++) {
        __syncthreads();
        {
            const float4* wsrc = (const float4*)(W + (size_t)l * DD * DD);
            for (int i = tid; i < DD * DD / 4; i += 256)
                ((float4*)Ws)[i] = wsrc[i];
        }
        __syncthreads();

        unsigned long long acc2[2][4];
        #pragma unroll
        for (int i = 0; i < 2; i++)
            #pragma unroll
            for (int jp = 0; jp < 4; jp++) acc2[i][jp] = 0ULL;

        #pragma unroll 8
        for (int k = 0; k < 64; k++) {
            unsigned long long a2[2];
            #pragma unroll
            for (int i = 0; i < 2; i++) {
                float a = As[k * 65 + rg + 32 * i];
                a2[i] = pack2(a, a);
            }
            const unsigned long long* wv =
                (const unsigned long long*)(Ws + k * 64 + cg * 8);
            #pragma unroll
            for (int jp = 0; jp < 4; jp++) {
                unsigned long long w2 = wv[jp];
                #pragma unroll
                for (int i = 0; i < 2; i++)
                    acc2[i][jp] = fma2(a2[i], w2, acc2[i][jp]);
            }
        }

        __syncthreads();   // all reads of As done before overwrite

        #pragma unroll
        for (int i = 0; i < 2; i++) {
            const int row = rg + 32 * i;
            #pragma unroll
            for (int jp = 0; jp < 4; jp++) {
                float2 v  = unpack2(acc2[i][jp]);
                const int j0 = cg * 8 + jp * 2;
                float2 bb = *(const float2*)(B + l * 64 + j0);
                float o0 = v.x + bb.x;
                float o1 = v.y + bb.y;
                if (l < 2) {
                    o0 = fmaxf(o0, 0.0f);
                    o1 = fmaxf(o1, 0.0f);
                    As[(j0 + 0) * 65 + row] = o0;
                    As[(j0 + 1) * 65 + row] = o1;
                } else if (u == 0) {
                    *(float2*)(g_Q + (size_t)(base + row) * 64 + j0) = make_float2(o0, o1);
                } else {
                    g_KT[(size_t)((u - 1) * 64 + j0    ) * TT + base + row] = o0;
                    g_KT[(size_t)((u - 1) * 64 + j0 + 1) * TT + base + row] = o1;
                }
            }
        }
    }
}

// ---------------- Kernel 2: extract V (channels 0,1) and times ----------------
__global__ void __launch_bounds__(256) k_prep(const float* __restrict__ X)
{
    const int m = blockIdx.y;
    const int t = blockIdx.x * 256 + threadIdx.x;
    const float* xr = X + ((size_t)m * TT + t) * DD;
    float2 v;
    v.x = xr[0];
    v.y = xr[1];
    ((float2*)g_V2)[(size_t)m * TT + t] = v;
    g_T2[(size_t)m * TT + t] = xr[63];
}

// ---------------- Kernel 3a: per-segment totals ----------------
// grid = 256 channels * 8 segments. Each block: 1024 elements, 4 per thread.
__global__ void __launch_bounds__(256) k_scan1()
{
    const int ch  = blockIdx.x >> 3;      // m*64+d
    const int seg = blockIdx.x & 7;
    const int m   = ch >> 6;
    const int tid = threadIdx.x;
    const int t0  = seg * SEG + tid * 4;

    const float4 k4 = ((const float4*)(g_KT + (size_t)ch * TT))[t0 >> 2];
    const float4 va = ((const float4*)(g_V2 + (size_t)m * TT * 2))[t0 >> 1];
    const float4 vb = ((const float4*)(g_V2 + (size_t)m * TT * 2))[(t0 >> 1) + 1];

    float s0 = k4.x * va.x + k4.y * va.z + k4.z * vb.x + k4.w * vb.z;
    float s1 = k4.x * va.y + k4.y * va.w + k4.z * vb.y + k4.w * vb.w;

    __shared__ float ws0[8], ws1[8];
    const int lane = tid & 31, wid = tid >> 5;
    #pragma unroll
    for (int off = 16; off > 0; off >>= 1) {
        s0 += __shfl_down_sync(0xffffffffu, s0, off);
        s1 += __shfl_down_sync(0xffffffffu, s1, off);
    }
    if (lane == 0) { ws0[wid] = s0; ws1[wid] = s1; }
    __syncthreads();
    if (tid == 0) {
        float a = 0, b = 0;
        #pragma unroll
        for (int w = 0; w < 8; w++) { a += ws0[w]; b += ws1[w]; }
        ((float2*)g_seg)[ch * NSEG + seg] = make_float2(a, b);
    }
}

// ---------------- Kernel 3b: per-segment inclusive scan with base offset ----
__global__ void __launch_bounds__(256) k_scan2()
{
    const int ch  = blockIdx.x >> 3;
    const int seg = blockIdx.x & 7;
    const int m   = ch >> 6;
    const int tid = threadIdx.x;
    const int t0  = seg * SEG + tid * 4;

    // base = sum of preceding segment totals (redundant per thread, cheap)
    float base0 = 0.0f, base1 = 0.0f;
    for (int s = 0; s < seg; s++) {
        float2 v = ((const float2*)g_seg)[ch * NSEG + s];
        base0 += v.x; base1 += v.y;
    }

    const float4 k4 = ((const float4*)(g_KT + (size_t)ch * TT))[t0 >> 2];
    const float4 va = ((const float4*)(g_V2 + (size_t)m * TT * 2))[t0 >> 1];
    const float4 vb = ((const float4*)(g_V2 + (size_t)m * TT * 2))[(t0 >> 1) + 1];

    float p0[4], p1[4];
    p0[0] = k4.x * va.x;  p1[0] = k4.x * va.y;
    p0[1] = k4.y * va.z;  p1[1] = k4.y * va.w;
    p0[2] = k4.z * vb.x;  p1[2] = k4.z * vb.y;
    p0[3] = k4.w * vb.z;  p1[3] = k4.w * vb.w;
    #pragma unroll
    for (int e = 1; e < 4; e++) { p0[e] += p0[e - 1]; p1[e] += p1[e - 1]; }

    // warp inclusive scan of thread totals
    const int lane = tid & 31, wid = tid >> 5;
    float s0 = p0[3], s1 = p1[3];
    const float t00 = s0, t11 = s1;
    #pragma unroll
    for (int off = 1; off < 32; off <<= 1) {
        float n0 = __shfl_up_sync(0xffffffffu, s0, off);
        float n1 = __shfl_up_sync(0xffffffffu, s1, off);
        if (lane >= off) { s0 += n0; s1 += n1; }
    }
    __shared__ float ws0[8], ws1[8];
    if (lane == 31) { ws0[wid] = s0; ws1[wid] = s1; }
    __syncthreads();
    float off0 = 0, off1 = 0;
    #pragma unroll
    for (int w = 0; w < 8; w++) {
        if (w < wid) { off0 += ws0[w]; off1 += ws1[w]; }
    }
    base0 += off0 + (s0 - t00);
    base1 += off1 + (s1 - t11);

    float4* sp = (float4*)(g_S + (size_t)ch * TT * 2);
    float4 o1, o2;
    o1.x = base0 + p0[0]; o1.y = base1 + p1[0];
    o1.z = base0 + p0[1]; o1.w = base1 + p1[1];
    o2.x = base0 + p0[2]; o2.y = base1 + p1[2];
    o2.z = base0 + p0[3]; o2.w = base1 + p1[3];
    sp[t0 >> 1]       = o1;
    sp[(t0 >> 1) + 1] = o2;
}

// ---------------- Kernel 4: fused searchsorted + gather + contract ----------
// grid (T/128, M), 256 threads: (t_local in 0..127, d-half in {0,1}).
__global__ void __launch_bounds__(256) k_gather()
{
    __shared__ float Qs[128 * 65];
    const int m  = blockIdx.y;
    const int t0 = blockIdx.x * 128;

    for (int i = threadIdx.x; i < 128 * 64; i += 256) {
        int r = i >> 6, dd = i & 63;
        Qs[r * 65 + dd] = g_Q[(size_t)(t0 + r) * 64 + dd];
    }
    __syncthreads();

    const int lt = threadIdx.x & 127;
    const int dh = threadIdx.x >> 7;
    const int t  = t0 + lt;

    // searchsorted(t2_m, t1[t], 'right') - 1
    const float key = g_T2[t];
    const float* arr = g_T2 + (size_t)m * TT;
    int lo = 0, hi = TT;
    while (lo < hi) {
        int mid = (lo + hi) >> 1;
        if (arr[mid] <= key) lo = mid + 1; else hi = mid;
    }
    const int idx = lo - 1;

    float a0 = 0.0f, a1 = 0.0f;
    if (idx >= 0) {
        const float2* sp = (const float2*)g_S;
        #pragma unroll
        for (int dd = 0; dd < 32; dd++) {
            const int d = dh * 32 + dd;
            float q  = Qs[lt * 65 + d];
            float2 s = sp[(size_t)(m * 64 + d) * TT + idx];
            a0 += q * s.x;
            a1 += q * s.y;
        }
    }
    g_part[((size_t)(m * 2 + dh) * TT + t) * 2 + 0] = a0;
    g_part[((size_t)(m * 2 + dh) * TT + t) * 2 + 1] = a1;
}

// ---------------- Kernel 5: deterministic reduction over 8 partials --------
__global__ void __launch_bounds__(256) k_reduce(float* __restrict__ out)
{
    const int t = blockIdx.x * 256 + threadIdx.x;
    const float2* pp = (const float2*)g_part;
    float ax = 0.0f, ay = 0.0f;
    #pragma unroll
    for (int s = 0; s < 8; s++) {
        float2 v = pp[(size_t)s * TT + t];
        ax += v.x; ay += v.y;
    }
    ((float2*)out)[t] = make_float2(ax, ay);
}

// ---------------- launch ----------------
extern "C" void kernel_launch(void* const* d_in, const int* in_sizes, int n_in,
                              void* d_out, int out_size)
{
    const float* X    = (const float*)d_in[0];
    const float* wq_w = (const float*)d_in[1];
    const float* wq_b = (const float*)d_in[2];
    const float* wk_w = (const float*)d_in[3];
    const float* wk_b = (const float*)d_in[4];
    float* out = (float*)d_out;

    const int SMEM1 = (64 * 65 + 64 * 64) * (int)sizeof(float);   // 33024 B
    cudaFuncSetAttribute(k_mlp, cudaFuncAttributeMaxDynamicSharedMemorySize, SMEM1);

    k_mlp   <<<dim3(TT / 64, 5), 256, SMEM1>>>(X, wq_w, wq_b, wk_w, wk_b);
    k_prep  <<<dim3(TT / 256, MM), 256>>>(X);
    k_scan1 <<<MM * DD * NSEG, 256>>>();
    k_scan2 <<<MM * DD * NSEG, 256>>>();
    k_gather<<<dim3(TT / 128, MM), 256>>>();
    k_reduce<<<TT / 256, 256>>>(out);
}

// round 3
// speedup vs baseline: 1.1093x; 1.0671x over previous
#include <cuda_runtime.h>
#include <cuda_bf16.h>

#define TT 8192
#define DD 64
#define MM 4
#define NSEG 4
#define SEG 2048

// ---------------- scratch (device globals; no allocation) ----------------
__device__ float g_Q [TT * DD];            // Q row-major [t][d]           2MB
__device__ float g_KT[MM * DD * TT];       // K transposed [m][d][t]       8MB
__device__ float g_V2[MM * TT * 2];        // V interleaved [m][t][e]      256KB
__device__ float g_T2[MM * TT];            // t2 per modality (t1 = m=0)
__device__ float g_S [MM * DD * TT * 2];   // prefix sums [m][d][t][e]     16MB
__device__ float g_seg[MM * DD * NSEG * 2];// per-segment totals

// ---------------- packed f32x2 helpers ----------------
__device__ __forceinline__ unsigned long long pack2(float lo, float hi) {
    unsigned long long r;
    asm("mov.b64 %0, {%1, %2};" : "=l"(r) : "f"(lo), "f"(hi));
    return r;
}
__device__ __forceinline__ unsigned long long fma2(unsigned long long a,
                                                   unsigned long long b,
                                                   unsigned long long c) {
    unsigned long long d;
    asm("fma.rn.f32x2 %0, %1, %2, %3;" : "=l"(d) : "l"(a), "l"(b), "l"(c));
    return d;
}
__device__ __forceinline__ float2 unpack2(unsigned long long v) {
    float2 r;
    asm("mov.b64 {%0, %1}, %2;" : "=f"(r.x), "=f"(r.y) : "l"(v));
    return r;
}

// ---------------- Kernel 1: the 5 MLPs (Q and K_0..K_3) + V/t extraction --
// grid (T/64, 5), 128 threads. Thread computes 4 rows (rg+16i) x 8 cols
// (4 packed f32x2 accumulators per row).
__global__ void __launch_bounds__(128) k_mlp(
    const float* __restrict__ X,
    const float* __restrict__ wq_w, const float* __restrict__ wq_b,
    const float* __restrict__ wk_w, const float* __restrict__ wk_b)
{
    __shared__ float As[64 * 65];
    __shared__ float Ws[64 * 64];

    const int tid  = threadIdx.x;
    const int u    = blockIdx.y;                 // 0 -> Q, 1..4 -> K_{u-1}
    const int base = blockIdx.x * 64;
    const int m_in = (u == 0) ? 0 : (u - 1);
    const float* W = (u == 0) ? wq_w : wk_w + (size_t)(u - 1) * 3 * DD * DD;
    const float* B = (u == 0) ? wq_b : wk_b + (size_t)(u - 1) * 3 * DD;

    // load 64x64 A tile transposed into smem: As[d][row]
    {
        const int row = tid >> 1;          // 0..63
        const int hf  = tid & 1;           // 32-float half
        const float4* src = (const float4*)(X + ((size_t)m_in * TT + base + row) * DD + hf * 32);
        #pragma unroll
        for (int q = 0; q < 8; q++) {
            float4 v = src[q];
            int d0 = hf * 32 + q * 4;
            As[(d0 + 0) * 65 + row] = v.x;
            As[(d0 + 1) * 65 + row] = v.y;
            As[(d0 + 2) * 65 + row] = v.z;
            As[(d0 + 3) * 65 + row] = v.w;
        }
    }
    __syncthreads();

    // fused prep: V (d=0,1) and times (d=63) from the smem tile (K blocks only)
    if (u >= 1 && tid < 64) {
        const int t = base + tid;
        float2 v;
        v.x = As[0 * 65 + tid];
        v.y = As[1 * 65 + tid];
        ((float2*)g_V2)[(size_t)m_in * TT + t] = v;
        g_T2[(size_t)m_in * TT + t] = As[63 * 65 + tid];
    }

    const int rg = tid & 15;   // rows rg + 16*i, i<4
    const int cg = tid >> 4;   // cols cg*8 .. cg*8+7

    for (int l = 0; l < 3; l++) {
        if (l) __syncthreads();
        {
            const float4* wsrc = (const float4*)(W + (size_t)l * DD * DD);
            #pragma unroll
            for (int q = 0; q < 8; q++)
                ((float4*)Ws)[tid + 128 * q] = wsrc[tid + 128 * q];
        }
        __syncthreads();

        unsigned long long acc2[4][4];
        #pragma unroll
        for (int i = 0; i < 4; i++)
            #pragma unroll
            for (int jp = 0; jp < 4; jp++) acc2[i][jp] = 0ULL;

        #pragma unroll 4
        for (int k = 0; k < 64; k++) {
            unsigned long long a2[4];
            #pragma unroll
            for (int i = 0; i < 4; i++) {
                float a = As[k * 65 + rg + 16 * i];
                a2[i] = pack2(a, a);
            }
            const unsigned long long* wv =
                (const unsigned long long*)(Ws + k * 64 + cg * 8);
            #pragma unroll
            for (int jp = 0; jp < 4; jp++) {
                unsigned long long w2 = wv[jp];
                #pragma unroll
                for (int i = 0; i < 4; i++)
                    acc2[i][jp] = fma2(a2[i], w2, acc2[i][jp]);
            }
        }

        __syncthreads();   // all reads of As done before overwrite

        #pragma unroll
        for (int i = 0; i < 4; i++) {
            const int row = rg + 16 * i;
            #pragma unroll
            for (int jp = 0; jp < 4; jp++) {
                float2 v  = unpack2(acc2[i][jp]);
                const int j0 = cg * 8 + jp * 2;
                float2 bb = *(const float2*)(B + l * 64 + j0);
                float o0 = v.x + bb.x;
                float o1 = v.y + bb.y;
                if (l < 2) {
                    o0 = fmaxf(o0, 0.0f);
                    o1 = fmaxf(o1, 0.0f);
                    As[(j0 + 0) * 65 + row] = o0;
                    As[(j0 + 1) * 65 + row] = o1;
                } else if (u == 0) {
                    *(float2*)(g_Q + (size_t)(base + row) * 64 + j0) = make_float2(o0, o1);
                } else {
                    g_KT[(size_t)((u - 1) * 64 + j0    ) * TT + base + row] = o0;
                    g_KT[(size_t)((u - 1) * 64 + j0 + 1) * TT + base + row] = o1;
                }
            }
        }
    }
}

// ---------------- Kernel 2a: per-segment totals (8 elems/thread) ----------
__global__ void __launch_bounds__(256) k_scan1()
{
    const int ch  = blockIdx.x >> 2;      // m*64+d
    const int seg = blockIdx.x & 3;
    const int m   = ch >> 6;
    const int tid = threadIdx.x;
    const int t0  = seg * SEG + tid * 8;

    const float4* kp = (const float4*)(g_KT + (size_t)ch * TT);
    const float4* vp = (const float4*)(g_V2 + (size_t)m * TT * 2);
    float4 ka = kp[t0 >> 2], kb = kp[(t0 >> 2) + 1];
    float kk[8] = {ka.x, ka.y, ka.z, ka.w, kb.x, kb.y, kb.z, kb.w};

    float s0 = 0.0f, s1 = 0.0f;
    #pragma unroll
    for (int q = 0; q < 4; q++) {
        float4 v = vp[(t0 >> 1) + q];   // (e0,e1) pairs for elems 2q,2q+1
        s0 += kk[2 * q] * v.x + kk[2 * q + 1] * v.z;
        s1 += kk[2 * q] * v.y + kk[2 * q + 1] * v.w;
    }

    __shared__ float ws0[8], ws1[8];
    const int lane = tid & 31, wid = tid >> 5;
    #pragma unroll
    for (int off = 16; off > 0; off >>= 1) {
        s0 += __shfl_down_sync(0xffffffffu, s0, off);
        s1 += __shfl_down_sync(0xffffffffu, s1, off);
    }
    if (lane == 0) { ws0[wid] = s0; ws1[wid] = s1; }
    __syncthreads();
    if (tid == 0) {
        float a = 0, b = 0;
        #pragma unroll
        for (int w = 0; w < 8; w++) { a += ws0[w]; b += ws1[w]; }
        ((float2*)g_seg)[ch * NSEG + seg] = make_float2(a, b);
    }
}

// ---------------- Kernel 2b: per-segment inclusive scan with base ---------
__global__ void __launch_bounds__(256) k_scan2()
{
    const int ch  = blockIdx.x >> 2;
    const int seg = blockIdx.x & 3;
    const int m   = ch >> 6;
    const int tid = threadIdx.x;
    const int t0  = seg * SEG + tid * 8;

    float base0 = 0.0f, base1 = 0.0f;
    #pragma unroll
    for (int s = 0; s < NSEG - 1; s++) {
        if (s < seg) {
            float2 v = ((const float2*)g_seg)[ch * NSEG + s];
            base0 += v.x; base1 += v.y;
        }
    }

    const float4* kp = (const float4*)(g_KT + (size_t)ch * TT);
    const float4* vp = (const float4*)(g_V2 + (size_t)m * TT * 2);
    float4 ka = kp[t0 >> 2], kb = kp[(t0 >> 2) + 1];
    float kk[8] = {ka.x, ka.y, ka.z, ka.w, kb.x, kb.y, kb.z, kb.w};

    float p0[8], p1[8];
    #pragma unroll
    for (int q = 0; q < 4; q++) {
        float4 v = vp[(t0 >> 1) + q];
        p0[2 * q]     = kk[2 * q]     * v.x;
        p1[2 * q]     = kk[2 * q]     * v.y;
        p0[2 * q + 1] = kk[2 * q + 1] * v.z;
        p1[2 * q + 1] = kk[2 * q + 1] * v.w;
    }
    #pragma unroll
    for (int e = 1; e < 8; e++) { p0[e] += p0[e - 1]; p1[e] += p1[e - 1]; }

    const int lane = tid & 31, wid = tid >> 5;
    float s0 = p0[7], s1 = p1[7];
    const float t00 = s0, t11 = s1;
    #pragma unroll
    for (int off = 1; off < 32; off <<= 1) {
        float n0 = __shfl_up_sync(0xffffffffu, s0, off);
        float n1 = __shfl_up_sync(0xffffffffu, s1, off);
        if (lane >= off) { s0 += n0; s1 += n1; }
    }
    __shared__ float ws0[8], ws1[8];
    if (lane == 31) { ws0[wid] = s0; ws1[wid] = s1; }
    __syncthreads();
    #pragma unroll
    for (int w = 0; w < 7; w++) {
        if (w < wid) { base0 += ws0[w]; base1 += ws1[w]; }
    }
    base0 += s0 - t00;
    base1 += s1 - t11;

    float4* sp = (float4*)(g_S + (size_t)ch * TT * 2);
    #pragma unroll
    for (int q = 0; q < 4; q++) {
        float4 o;
        o.x = base0 + p0[2 * q];     o.y = base1 + p1[2 * q];
        o.z = base0 + p0[2 * q + 1]; o.w = base1 + p1[2 * q + 1];
        sp[(t0 >> 1) + q] = o;
    }
}

// ---------------- Kernel 3: fused searchsorted + gather + contract + sum --
// grid (T/64), 256 threads: (t_local 0..63, dq 0..3 each owning 16 d's).
// Loops all 4 modalities, deterministic reduction, writes final output.
__global__ void __launch_bounds__(256) k_out(float* __restrict__ out)
{
    __shared__ float Qs[64 * 65];
    __shared__ int   idxs[MM][64];
    __shared__ float2 red[256];

    const int t0  = blockIdx.x * 64;
    const int tid = threadIdx.x;
    const int lt  = tid & 63;
    const int dq  = tid >> 6;

    // load Q tile [64 t][64 d]
    {
        const int r = tid >> 2, c4 = tid & 3;
        const float4* src = (const float4*)(g_Q + (size_t)(t0 + r) * 64 + c4 * 16);
        #pragma unroll
        for (int q = 0; q < 4; q++) {
            float4 v = src[q];
            int d0 = c4 * 16 + q * 4;
            Qs[r * 65 + d0 + 0] = v.x;
            Qs[r * 65 + d0 + 1] = v.y;
            Qs[r * 65 + d0 + 2] = v.z;
            Qs[r * 65 + d0 + 3] = v.w;
        }
    }

    // binary search: thread (lt, dq) does modality m = dq for query t0+lt
    {
        const int m = dq;
        const float key = g_T2[t0 + lt];
        const float* arr = g_T2 + (size_t)m * TT;
        int lo = 0, hi = TT;
        while (lo < hi) {
            int mid = (lo + hi) >> 1;
            if (arr[mid] <= key) lo = mid + 1; else hi = mid;
        }
        idxs[m][lt] = lo - 1;
    }
    __syncthreads();

    float a0 = 0.0f, a1 = 0.0f;
    const float2* sp = (const float2*)g_S;
    #pragma unroll
    for (int m = 0; m < MM; m++) {
        const int idx = idxs[m][lt];
        if (idx >= 0) {
            #pragma unroll
            for (int dd = 0; dd < 16; dd++) {
                const int d = dq * 16 + dd;
                float q  = Qs[lt * 65 + d];
                float2 s = sp[(size_t)(m * 64 + d) * TT + idx];
                a0 += q * s.x;
                a1 += q * s.y;
            }
        }
    }
    red[tid] = make_float2(a0, a1);
    __syncthreads();

    if (dq == 0) {
        float ax = 0.0f, ay = 0.0f;
        #pragma unroll
        for (int q = 0; q < 4; q++) {
            float2 v = red[lt + 64 * q];
            ax += v.x; ay += v.y;
        }
        ((float2*)out)[t0 + lt] = make_float2(ax, ay);
    }
}

// ---------------- launch ----------------
extern "C" void kernel_launch(void* const* d_in, const int* in_sizes, int n_in,
                              void* d_out, int out_size)
{
    const float* X    = (const float*)d_in[0];
    const float* wq_w = (const float*)d_in[1];
    const float* wq_b = (const float*)d_in[2];
    const float* wk_w = (const float*)d_in[3];
    const float* wk_b = (const float*)d_in[4];
    float* out = (float*)d_out;

    k_mlp  <<<dim3(TT / 64, 5), 128>>>(X, wq_w, wq_b, wk_w, wk_b);
    k_scan1<<<MM * DD * NSEG, 256>>>();
    k_scan2<<<MM * DD * NSEG, 256>>>();
    k_out  <<<TT / 64, 256>>>(out);
}